// round 2
// baseline (speedup 1.0000x reference)
#include <cuda_runtime.h>
#include <cstdint>
#include <cstddef>

#define BSZ   64
#define NI    2048
#define DI    8
#define NO    32
#define DOUT  16

#define BT    32          // batches per b-tile
#define NCH   4           // n's per work item
#define NTHREADS 512
#define GRID  148
#define N_ITEMS ((NI / NCH) * (BSZ / BT))   // 512 * 2 = 1024

typedef unsigned long long ull;

__device__ float g_s[BSZ * NO * DOUT];          // 128 KB accumulator (zeroed by squash)
__device__ float g_v[BSZ * NO * DOUT];          // previous iteration v
__device__ float g_blog[(size_t)BSZ * NI * NO]; // 16 MB routing logits

__device__ __forceinline__ unsigned swz(unsigned byte_off) {
    return byte_off ^ ((byte_off >> 3) & 0x70);
}
__device__ __forceinline__ ull pack2(float lo, float hi) {
    ull r; asm("mov.b64 %0,{%1,%2};" : "=l"(r) : "f"(lo), "f"(hi)); return r;
}
__device__ __forceinline__ float2 unpk(ull v) {
    float2 r; asm("mov.b64 {%0,%1},%2;" : "=f"(r.x), "=f"(r.y) : "l"(v)); return r;
}
__device__ __forceinline__ ull fma2(ull a, ull b, ull c) {
    ull d; asm("fma.rn.f32x2 %0,%1,%2,%3;" : "=l"(d) : "l"(a), "l"(b), "l"(c)); return d;
}
__device__ __forceinline__ ull mul2(ull a, ull b) {
    ull d; asm("mul.rn.f32x2 %0,%1,%2;" : "=l"(d) : "l"(a), "l"(b)); return d;
}

// Fused routing pass. PASS0: c=1/32. PASS1: t=v0.xhat, store blog, softmax.
// PASS2: t=blog+v1.xhat, softmax. All accumulate s into g_s via one atomic flush per b-tile.
template <int PASS>
__global__ void __launch_bounds__(NTHREADS, 1)
caps_pass(const float* __restrict__ X, const float* __restrict__ W)
{
    extern __shared__ char smraw[];
    float*  w_s = (float*)smraw;                           // 65536 B (4 n's, swizzled)
    float2* x_d = (float2*)(smraw + 65536);                // 8192 B (x duplicated pairs)
    float*  v_s = (float*)(smraw + 65536 + 8192);          // 65536 B
    float*  red = (float*)(smraw + 65536 + 8192 + 65536);  // 512 B (double-buffered)

    const int tid = threadIdx.x;
    const int wg  = tid >> 7;       // warpgroup: 8 batches
    const int wt  = tid & 127;
    const int o   = wt >> 2;        // output capsule 0..31
    const int dg  = wt & 3;         // d-quad

    const ull Z = pack2(0.f, 0.f);
    ull sacc[8][2];
#pragma unroll
    for (int b = 0; b < 8; b++) { sacc[b][0] = Z; sacc[b][1] = Z; }

    int cur_bt = -1;

    for (int it = blockIdx.x; it < N_ITEMS; it += gridDim.x) {
        const int btile = it >> 9;           // NI/NCH = 512 items per b-tile
        const int n0    = (it & 511) * NCH;
        const bool newb = (btile != cur_bt);

        if (newb && cur_bt >= 0) {
#pragma unroll
            for (int bi = 0; bi < 8; bi++) {
                float* p = g_s + (size_t)(cur_bt * BT + wg * 8 + bi) * 512 + o * 16 + dg * 4;
                float2 a = unpk(sacc[bi][0]); float2 b = unpk(sacc[bi][1]);
                atomicAdd(p + 0, a.x); atomicAdd(p + 1, a.y);
                atomicAdd(p + 2, b.x); atomicAdd(p + 3, b.y);
                sacc[bi][0] = Z; sacc[bi][1] = Z;
            }
        }
        __syncthreads();   // prior item done with w_s/x_d

        // Stage W for 4 n's (coalesced, swizzled)
#pragma unroll
        for (int k = 0; k < 8; k++) {
            int f = k * 2048 + tid * 4;
            float4 t4 = *(const float4*)(W + (size_t)n0 * 4096 + f);
            int nn = f >> 12, wi = f & 4095;
            *(float4*)((char*)w_s + nn * 16384 + swz((unsigned)wi * 4u)) = t4;
        }
        // Stage x duplicated into (x,x) pairs
        {
            int f = tid * 2;
            int bb = f >> 5, rem = f & 31;
            float2 t2 = *(const float2*)(X + (size_t)(btile * BT + bb) * (NI * DI) + n0 * DI + rem);
            x_d[f]     = make_float2(t2.x, t2.x);
            x_d[f + 1] = make_float2(t2.y, t2.y);
        }
        if (PASS > 0 && newb) {
#pragma unroll
            for (int k = 0; k < 8; k++) {
                int f = k * 2048 + tid * 4;
                *(float4*)(v_s + f) = *(const float4*)(g_v + (size_t)btile * BT * 512 + f);
            }
        }
        cur_bt = btile;
        __syncthreads();

#pragma unroll
        for (int nn = 0; nn < NCH; nn++) {
            const int n = n0 + nn;
            // Load + pack W: pairs across adjacent d, per i. wp[p][i] = (W[d0,i], W[d1,i])
            ull wp[2][8];
#pragma unroll
            for (int p = 0; p < 2; p++) {
                unsigned y0 = (unsigned)((o * 128 + (dg * 4 + 2 * p) * 8) * 4);
                unsigned y1 = (unsigned)((o * 128 + (dg * 4 + 2 * p + 1) * 8) * 4);
                const char* wb = (const char*)w_s + nn * 16384;
                float4 a0 = *(const float4*)(wb + swz(y0));
                float4 a1 = *(const float4*)(wb + swz(y0 + 16));
                float4 c0 = *(const float4*)(wb + swz(y1));
                float4 c1 = *(const float4*)(wb + swz(y1 + 16));
                wp[p][0] = pack2(a0.x, c0.x); wp[p][1] = pack2(a0.y, c0.y);
                wp[p][2] = pack2(a0.z, c0.z); wp[p][3] = pack2(a0.w, c0.w);
                wp[p][4] = pack2(a1.x, c1.x); wp[p][5] = pack2(a1.y, c1.y);
                wp[p][6] = pack2(a1.z, c1.z); wp[p][7] = pack2(a1.w, c1.w);
            }

            if (PASS == 0) {
                const ull C = pack2(0.03125f, 0.03125f);
#pragma unroll
                for (int bi = 0; bi < 8; bi++) {
                    const ulonglong2* xq = (const ulonglong2*)(x_d + (wg * 8 + bi) * 32 + nn * 8);
                    ulonglong2 q0 = xq[0], q1 = xq[1], q2 = xq[2], q3 = xq[3];
                    ull h0 = Z, h1 = Z;
                    h0 = fma2(wp[0][0], q0.x, h0); h1 = fma2(wp[1][0], q0.x, h1);
                    h0 = fma2(wp[0][1], q0.y, h0); h1 = fma2(wp[1][1], q0.y, h1);
                    h0 = fma2(wp[0][2], q1.x, h0); h1 = fma2(wp[1][2], q1.x, h1);
                    h0 = fma2(wp[0][3], q1.y, h0); h1 = fma2(wp[1][3], q1.y, h1);
                    h0 = fma2(wp[0][4], q2.x, h0); h1 = fma2(wp[1][4], q2.x, h1);
                    h0 = fma2(wp[0][5], q2.y, h0); h1 = fma2(wp[1][5], q2.y, h1);
                    h0 = fma2(wp[0][6], q3.x, h0); h1 = fma2(wp[1][6], q3.x, h1);
                    h0 = fma2(wp[0][7], q3.y, h0); h1 = fma2(wp[1][7], q3.y, h1);
                    sacc[bi][0] = fma2(C, h0, sacc[bi][0]);
                    sacc[bi][1] = fma2(C, h1, sacc[bi][1]);
                }
            } else {
#pragma unroll
                for (int g = 0; g < 2; g++) {
                    ull xh0[4], xh1[4];
                    float ee[4], bp[4];
                    if (PASS == 2) {
#pragma unroll
                        for (int q = 0; q < 4; q++)
                            bp[q] = (dg == 0)
                                ? g_blog[(size_t)(cur_bt * BT + wg * 8 + g * 4 + q) * (NI * NO) + (size_t)n * NO + o]
                                : 0.f;
                    }
#pragma unroll
                    for (int q = 0; q < 4; q++) {
                        const int bloc = wg * 8 + g * 4 + q;
                        const ulonglong2* xq = (const ulonglong2*)(x_d + bloc * 32 + nn * 8);
                        ulonglong2 q0 = xq[0], q1 = xq[1], q2 = xq[2], q3 = xq[3];
                        ull h0 = Z, h1 = Z;
                        h0 = fma2(wp[0][0], q0.x, h0); h1 = fma2(wp[1][0], q0.x, h1);
                        h0 = fma2(wp[0][1], q0.y, h0); h1 = fma2(wp[1][1], q0.y, h1);
                        h0 = fma2(wp[0][2], q1.x, h0); h1 = fma2(wp[1][2], q1.x, h1);
                        h0 = fma2(wp[0][3], q1.y, h0); h1 = fma2(wp[1][3], q1.y, h1);
                        h0 = fma2(wp[0][4], q2.x, h0); h1 = fma2(wp[1][4], q2.x, h1);
                        h0 = fma2(wp[0][5], q2.y, h0); h1 = fma2(wp[1][5], q2.y, h1);
                        h0 = fma2(wp[0][6], q3.x, h0); h1 = fma2(wp[1][6], q3.x, h1);
                        h0 = fma2(wp[0][7], q3.y, h0); h1 = fma2(wp[1][7], q3.y, h1);
                        xh0[q] = h0; xh1[q] = h1;

                        const ulonglong2 vv = *(const ulonglong2*)(v_s + (bloc * NO + o) * DOUT + dg * 4);
                        ull tp = fma2(h1, vv.y, mul2(h0, vv.x));
                        float2 tf = unpk(tp);
                        float t = tf.x + tf.y;
                        if (PASS == 2 && dg == 0) t += bp[q];
                        t += __shfl_xor_sync(0xffffffffu, t, 1);
                        t += __shfl_xor_sync(0xffffffffu, t, 2);   // full dot over 16 d (+blog)
                        if (PASS == 1 && dg == 0)
                            g_blog[(size_t)(cur_bt * BT + bloc) * (NI * NO) + (size_t)n * NO + o] = t;

                        float e_ = __expf(t);   // |t| <~ 1: no max-subtraction needed
                        ee[q] = e_;
                        float ws = e_;
                        ws += __shfl_xor_sync(0xffffffffu, ws, 4);
                        ws += __shfl_xor_sync(0xffffffffu, ws, 8);
                        ws += __shfl_xor_sync(0xffffffffu, ws, 16); // sum over 8 o in warp
                        if ((tid & 31) == 0) red[g * 64 + wg * 16 + q * 4 + (wt >> 5)] = ws;
                    }
                    asm volatile("bar.sync %0, 128;" :: "r"(wg + 1) : "memory");
#pragma unroll
                    for (int q = 0; q < 4; q++) {
                        const int bi = g * 4 + q;
                        float4 r4 = *(const float4*)(red + g * 64 + wg * 16 + q * 4);
                        float c = __fdividef(ee[q], (r4.x + r4.y) + (r4.z + r4.w));
                        ull cc = pack2(c, c);
                        sacc[bi][0] = fma2(cc, xh0[q], sacc[bi][0]);
                        sacc[bi][1] = fma2(cc, xh1[q], sacc[bi][1]);
                    }
                }
            }
        }
    }

    // Final flush
#pragma unroll
    for (int bi = 0; bi < 8; bi++) {
        float* p = g_s + (size_t)(cur_bt * BT + wg * 8 + bi) * 512 + o * 16 + dg * 4;
        float2 a = unpk(sacc[bi][0]); float2 b = unpk(sacc[bi][1]);
        atomicAdd(p + 0, a.x); atomicAdd(p + 1, a.y);
        atomicAdd(p + 2, b.x); atomicAdd(p + 3, b.y);
    }
}

// v = squash(s); also re-zeros g_s. float4 per thread (4 threads per 16-d row).
__global__ void squash_k(float* __restrict__ extout)
{
    int t = blockIdx.x * 256 + threadIdx.x;   // 8192 threads
    float4 s4 = *(const float4*)(g_s + t * 4);
    float sq = s4.x * s4.x + s4.y * s4.y + s4.z * s4.z + s4.w * s4.w;
    sq += __shfl_xor_sync(0xffffffffu, sq, 1);
    sq += __shfl_xor_sync(0xffffffffu, sq, 2);   // ||s||^2 over 16 d
    float f = sqrtf(sq) / (1.0f + sq);
    float4 v4 = make_float4(s4.x * f, s4.y * f, s4.z * f, s4.w * f);
    float* dst = extout ? extout : g_v;
    *(float4*)(dst + t * 4) = v4;
    *(float4*)(g_s + t * 4) = make_float4(0.f, 0.f, 0.f, 0.f);
}

extern "C" void kernel_launch(void* const* d_in, const int* in_sizes, int n_in,
                              void* d_out, int out_size)
{
    const float* X = (const float*)d_in[0];
    const float* W = (const float*)d_in[1];
    if (in_sizes[0] != BSZ * NI * DI) { X = (const float*)d_in[1]; W = (const float*)d_in[0]; }

    const int smem = 65536 + 8192 + 65536 + 512;  // 139776 B
    cudaFuncSetAttribute(caps_pass<0>, cudaFuncAttributeMaxDynamicSharedMemorySize, smem);
    cudaFuncSetAttribute(caps_pass<1>, cudaFuncAttributeMaxDynamicSharedMemorySize, smem);
    cudaFuncSetAttribute(caps_pass<2>, cudaFuncAttributeMaxDynamicSharedMemorySize, smem);

    caps_pass<0><<<GRID, NTHREADS, smem>>>(X, W);
    squash_k<<<32, 256>>>((float*)nullptr);
    caps_pass<1><<<GRID, NTHREADS, smem>>>(X, W);
    squash_k<<<32, 256>>>((float*)nullptr);
    caps_pass<2><<<GRID, NTHREADS, smem>>>(X, W);
    squash_k<<<32, 256>>>((float*)d_out);
}